// round 2
// baseline (speedup 1.0000x reference)
#include <cuda_runtime.h>
#include <cuda_bf16.h>

// Rank-based average pooling: 2x2 window, stride 2, mean of top-2 values.
// x: [16,128,128,256] f32 NHWC  ->  out: [16,64,64,256] f32
//
// Streaming kernel, 2 output float4s per thread (split-half mapping keeps both
// halves fully coalesced). All 8 window loads are issued front-batched
// (MLP_p1=8) with streaming cache hints; stores are streaming too.

#define C4 64          // 256 channels / 4
#define WO 64
#define HO 64
#define W_IN 128

__device__ __forceinline__ float top2mean(float v0, float v1, float v2, float v3) {
    // sum of top-2 = total - smallest - second smallest
    float a = fminf(v0, v1), b = fmaxf(v0, v1);
    float c = fminf(v2, v3), d = fmaxf(v2, v3);
    float lo1 = fminf(a, c);
    float lo2 = fminf(fmaxf(a, c), fminf(b, d));
    return (v0 + v1 + v2 + v3 - lo1 - lo2) * 0.5f;
}

__device__ __forceinline__ long in_base(int idx) {
    int c4 = idx & (C4 - 1);
    int t  = idx >> 6;
    int wo = t & (WO - 1);
    t >>= 6;
    int ho = t & (HO - 1);
    int b  = t >> 6;
    return (((long)(b * 128 + 2 * ho) * W_IN) + 2 * wo) * C4 + c4;
}

__global__ void __launch_bounds__(256)
rank_pool_kernel(const float4* __restrict__ in, float4* __restrict__ out, int half) {
    int idx0 = blockIdx.x * blockDim.x + threadIdx.x;
    if (idx0 >= half) return;
    int idx1 = idx0 + half;

    const long ROW = (long)W_IN * C4;   // 8192 float4 per input row
    const long COL = C4;                // 64 float4 per pixel

    long b0 = in_base(idx0);
    long b1 = in_base(idx1);

    // Front-batch all 8 independent loads (streaming: no reuse anywhere).
    float4 a00 = __ldcs(in + b0);
    float4 a01 = __ldcs(in + b0 + COL);
    float4 a10 = __ldcs(in + b0 + ROW);
    float4 a11 = __ldcs(in + b0 + ROW + COL);
    float4 c00 = __ldcs(in + b1);
    float4 c01 = __ldcs(in + b1 + COL);
    float4 c10 = __ldcs(in + b1 + ROW);
    float4 c11 = __ldcs(in + b1 + ROW + COL);

    float4 r0, r1;
    r0.x = top2mean(a00.x, a01.x, a10.x, a11.x);
    r0.y = top2mean(a00.y, a01.y, a10.y, a11.y);
    r0.z = top2mean(a00.z, a01.z, a10.z, a11.z);
    r0.w = top2mean(a00.w, a01.w, a10.w, a11.w);
    r1.x = top2mean(c00.x, c01.x, c10.x, c11.x);
    r1.y = top2mean(c00.y, c01.y, c10.y, c11.y);
    r1.z = top2mean(c00.z, c01.z, c10.z, c11.z);
    r1.w = top2mean(c00.w, c01.w, c10.w, c11.w);

    __stcs(out + idx0, r0);
    __stcs(out + idx1, r1);
}

extern "C" void kernel_launch(void* const* d_in, const int* in_sizes, int n_in,
                              void* d_out, int out_size) {
    const float4* x = (const float4*)d_in[0];
    float4* o = (float4*)d_out;
    int n4 = out_size / 4;        // 4,194,304 output float4s
    int half = n4 / 2;            // 2,097,152
    int threads = 256;
    int blocks = (half + threads - 1) / threads;  // 8192
    rank_pool_kernel<<<blocks, threads>>>(x, o, half);
}

// round 3
// speedup vs baseline: 1.0073x; 1.0073x over previous
#include <cuda_runtime.h>
#include <cuda_bf16.h>

// Rank-based average pooling: 2x2 window, stride 2, mean of top-2 values.
// x: [16,128,128,256] f32 NHWC  ->  out: [16,64,64,256] f32
//
// One warp per output pixel. The two window columns are adjacent in memory,
// so each warp reads two fully-contiguous 2KB segments (top input row,
// bottom input row) and writes one contiguous 1KB output segment.
// Thread t owns channel-groups t and t+32 (float4 granularity).

#define F4_PER_PIXEL 64      // 256 ch / 4
#define ROW_F4 8192          // 128 pixels * 64 f4 per input row

__device__ __forceinline__ float top2mean(float v0, float v1, float v2, float v3) {
    float a = fminf(v0, v1), b = fmaxf(v0, v1);
    float c = fminf(v2, v3), d = fmaxf(v2, v3);
    float lo1 = fminf(a, c);
    float lo2 = fminf(fmaxf(a, c), fminf(b, d));
    return (v0 + v1 + v2 + v3 - lo1 - lo2) * 0.5f;
}

__device__ __forceinline__ float4 t2m4(float4 p00, float4 p01, float4 p10, float4 p11) {
    float4 r;
    r.x = top2mean(p00.x, p01.x, p10.x, p11.x);
    r.y = top2mean(p00.y, p01.y, p10.y, p11.y);
    r.z = top2mean(p00.z, p01.z, p10.z, p11.z);
    r.w = top2mean(p00.w, p01.w, p10.w, p11.w);
    return r;
}

__global__ void __launch_bounds__(256)
rank_pool_kernel(const float4* __restrict__ in, float4* __restrict__ out) {
    // global warp id = output pixel id
    int warp = (blockIdx.x * blockDim.x + threadIdx.x) >> 5;
    int t = threadIdx.x & 31;

    // pixel -> (b, ho, wo);  65536 pixels total
    int wo = warp & 63;
    int tmp = warp >> 6;
    int ho = tmp & 63;
    int b  = tmp >> 6;

    // top input row segment: pixels (2ho, 2wo) and (2ho, 2wo+1), contiguous 128 f4
    long top = (long)(b * 128 + 2 * ho) * ROW_F4 + (long)(2 * wo) * F4_PER_PIXEL;
    long bot = top + ROW_F4;

    // dense 2KB warp reads (streaming — zero reuse)
    float4 a0 = __ldcs(in + top + t);        // p00, ch-group t
    float4 a1 = __ldcs(in + top + t + 32);   // p00, ch-group t+32
    float4 a2 = __ldcs(in + top + t + 64);   // p01, ch-group t
    float4 a3 = __ldcs(in + top + t + 96);   // p01, ch-group t+32
    float4 b0 = __ldcs(in + bot + t);        // p10, ch-group t
    float4 b1 = __ldcs(in + bot + t + 32);   // p10, ch-group t+32
    float4 b2 = __ldcs(in + bot + t + 64);   // p11, ch-group t
    float4 b3 = __ldcs(in + bot + t + 96);   // p11, ch-group t+32

    float4 r0 = t2m4(a0, a2, b0, b2);        // ch-group t
    float4 r1 = t2m4(a1, a3, b1, b3);        // ch-group t+32

    long obase = (long)warp * F4_PER_PIXEL;
    __stcs(out + obase + t, r0);
    __stcs(out + obase + t + 32, r1);
}

extern "C" void kernel_launch(void* const* d_in, const int* in_sizes, int n_in,
                              void* d_out, int out_size) {
    const float4* x = (const float4*)d_in[0];
    float4* o = (float4*)d_out;
    // 65536 output pixels, 1 warp each -> 65536 warps -> 8192 blocks of 256 thr
    int blocks = 8192;
    rank_pool_kernel<<<blocks, 256>>>(x, o);
}